// round 8
// baseline (speedup 1.0000x reference)
#include <cuda_runtime.h>
#include <cuda_bf16.h>
#include <cstdint>

// ---------------------------------------------------------------------------
// AggrEGATConv fused EGAT convolution.
//   output: res_n [N,16] followed by res_e [E,16], f32
// ---------------------------------------------------------------------------

#define MAXN 100000
#define MAXE 1600000

__device__ float g_fni [(size_t)MAXN * 64];
__device__ float g_fnj [(size_t)MAXN * 64];
__device__ float g_hsrc[(size_t)MAXN * 64];
__device__ float g_ex  [(size_t)MAXE * 4];
__device__ float g_z   [(size_t)MAXN * 4];
// W_fij split into bf16 hi/lo, transposed (wt[n][kp]), packed (k,k+1) u32
__device__ unsigned g_wth[64 * 32];
__device__ unsigned g_wtl[64 * 32];
// node weights (W_ni, W_nj, W_src), same transposed bf16 hi/lo form, K=128
__device__ unsigned g_wnh[3 * 64 * 64];
__device__ unsigned g_wnl[3 * 64 * 64];

// ---- helpers ---------------------------------------------------------------
__device__ __forceinline__ void red_add_v4(float* p, float a, float b,
                                           float c, float d) {
    asm volatile("red.global.add.v4.f32 [%0], {%1, %2, %3, %4};"
                 :: "l"(p), "f"(a), "f"(b), "f"(c), "f"(d) : "memory");
}
__device__ __forceinline__ unsigned bf16pack(float lo_elem, float hi_elem) {
    unsigned short ulo = __bfloat16_as_ushort(__float2bfloat16(lo_elem));
    unsigned short uhi = __bfloat16_as_ushort(__float2bfloat16(hi_elem));
    return (unsigned)ulo | ((unsigned)uhi << 16);
}
__device__ __forceinline__ float bf16residual(float x) {
    return x - __bfloat162float(__float2bfloat16(x));
}
__device__ __forceinline__ void mma16816(float& d0, float& d1, float& d2,
                                         float& d3, unsigned a0, unsigned a1,
                                         unsigned a2, unsigned a3,
                                         unsigned b0, unsigned b1) {
    asm volatile(
        "mma.sync.aligned.m16n8k16.row.col.f32.bf16.bf16.f32 "
        "{%0,%1,%2,%3}, {%4,%5,%6,%7}, {%8,%9}, {%0,%1,%2,%3};"
        : "+f"(d0), "+f"(d1), "+f"(d2), "+f"(d3)
        : "r"(a0), "r"(a1), "r"(a2), "r"(a3), "r"(b0), "r"(b1));
}

// edge_main strides (words): 36 mod 32 == 4 -> conflict-free; even -> aligned
#define XS     36
#define WS     36
#define WREG   1152
// node_mma strides: 68 mod 32 == 4 -> conflict-free; even -> aligned
#define NXS    68
#define NWREG  2176       // 2 * 16 * NXS

// ---------------------------------------------------------------------------
// Kernels 0a/0b: zero res_n and z.
// ---------------------------------------------------------------------------
__global__ void zero_n(float* __restrict__ out_n, int N) {
    int i = blockIdx.x * 256 + threadIdx.x;
    if (i < N * 16) out_n[i] = 0.0f;
}
__global__ void zero_z(int N) {
    int i = blockIdx.x * 256 + threadIdx.x;
    if (i < N * 4) g_z[i] = 0.0f;
}

// ---------------------------------------------------------------------------
// Kernel W: split all weights into bf16 hi/lo transposed fragment words.
//   jobs 0..2047:       edge W_fij  (kp 0..31)
//   jobs 2048..14335:   node Ws     (which, n, kp 0..63)
// ---------------------------------------------------------------------------
__global__ void wsplit_all(const float* __restrict__ Wfij,
                           const float* __restrict__ Wni,
                           const float* __restrict__ Wnj,
                           const float* __restrict__ Wsrc) {
    int j = blockIdx.x * 256 + threadIdx.x;
    if (j < 2048) {
        int n  = j >> 5;
        int kp = j & 31;
        float w0 = Wfij[(2 * kp) * 64 + n];
        float w1 = Wfij[(2 * kp + 1) * 64 + n];
        g_wth[j] = bf16pack(w0, w1);
        g_wtl[j] = bf16pack(bf16residual(w0), bf16residual(w1));
    } else if (j < 14336) {
        int t = j - 2048;
        int which = t >> 12;          // 0..2
        int r = t & 4095;
        int n  = r >> 6;              // 0..63
        int kp = r & 63;              // 0..63
        const float* W = (which == 0) ? Wni : (which == 1) ? Wnj : Wsrc;
        float w0 = W[(2 * kp) * 64 + n];
        float w1 = W[(2 * kp + 1) * 64 + n];
        g_wnh[t] = bf16pack(w0, w1);
        g_wnl[t] = bf16pack(bf16residual(w0), bf16residual(w1));
    }
}

// ---------------------------------------------------------------------------
// Kernel 1: node GEMMs via tensor cores (bf16x3).  grid=(tiles, 3 which).
//   8 warps/block, 128 nodes/block, 16 nodes/warp-tile, K=128 (8 kt).
// ---------------------------------------------------------------------------
__global__ __launch_bounds__(256, 2)
void node_mma(const float* __restrict__ nf,
              const float* __restrict__ bsrc,
              int N)
{
    extern __shared__ char dyns[];
    unsigned* s_wh = (unsigned*)dyns;                    // 64*NXS
    unsigned* s_wl = s_wh + 64 * NXS;                    // 64*NXS
    unsigned* s_x  = s_wl + 64 * NXS;                    // 8*NWREG
    float*    sb   = (float*)(s_x + 8 * NWREG);          // 64

    const int tid  = threadIdx.x;
    const int lane = tid & 31;
    const int w    = tid >> 5;
    const int which = blockIdx.y;

    const unsigned* wnh = g_wnh + which * 4096;
    const unsigned* wnl = g_wnl + which * 4096;
    for (int j = tid; j < 4096; j += 256) {
        int n = j >> 6, kp = j & 63;
        s_wh[n * NXS + kp] = wnh[j];
        s_wl[n * NXS + kp] = wnl[j];
    }
    if (tid < 64) sb[tid] = (which == 2) ? bsrc[tid] : 0.0f;

    // stage x rows (128 per block), coalesced, bf16 hi/lo split
    const int nbase = blockIdx.x * 128;
    {
        const float4* nf4 = (const float4*)nf;
#pragma unroll
        for (int i = 0; i < 16; ++i) {
            int idx = i * 256 + tid;             // 0..4095
            int r  = idx >> 5;                   // local row 0..127
            int ch = idx & 31;                   // float4 chunk 0..31
            float4 v = make_float4(0.f, 0.f, 0.f, 0.f);
            if (nbase + r < N) v = nf4[(size_t)(nbase + r) * 32 + ch];
            unsigned h0 = bf16pack(v.x, v.y);
            unsigned h1 = bf16pack(v.z, v.w);
            unsigned l0 = bf16pack(bf16residual(v.x), bf16residual(v.y));
            unsigned l1 = bf16pack(bf16residual(v.z), bf16residual(v.w));
            unsigned* base = s_x + (r >> 4) * NWREG + (r & 15) * NXS + ch * 2;
            *(uint2*)(base)            = make_uint2(h0, h1);
            *(uint2*)(base + 16 * NXS) = make_uint2(l0, l1);
        }
    }
    __syncthreads();

    const int g = lane >> 2;
    const int q = lane & 3;

    float acc[8][4];
#pragma unroll
    for (int nt = 0; nt < 8; ++nt)
#pragma unroll
        for (int i = 0; i < 4; ++i) acc[nt][i] = 0.0f;

    const unsigned* xh0 = s_x + w * NWREG + g * NXS;
    const unsigned* xh8 = xh0 + 8 * NXS;
    const unsigned* xl0 = xh0 + 16 * NXS;
    const unsigned* xl8 = xl0 + 8 * NXS;

#pragma unroll
    for (int kt = 0; kt < 8; ++kt) {
        const int kp = kt * 8 + q;
        unsigned ah0 = xh0[kp],     ah1 = xh8[kp];
        unsigned ah2 = xh0[kp + 4], ah3 = xh8[kp + 4];
        unsigned al0 = xl0[kp],     al1 = xl8[kp];
        unsigned al2 = xl0[kp + 4], al3 = xl8[kp + 4];
#pragma unroll
        for (int nt = 0; nt < 8; ++nt) {
            const unsigned* wb  = s_wh + (nt * 8 + g) * NXS + kp;
            const unsigned* wlb = s_wl + (nt * 8 + g) * NXS + kp;
            unsigned bh0 = wb[0],  bh1 = wb[4];
            unsigned bl0 = wlb[0], bl1 = wlb[4];
            mma16816(acc[nt][0], acc[nt][1], acc[nt][2], acc[nt][3],
                     ah0, ah1, ah2, ah3, bh0, bh1);
            mma16816(acc[nt][0], acc[nt][1], acc[nt][2], acc[nt][3],
                     ah0, ah1, ah2, ah3, bl0, bl1);
            mma16816(acc[nt][0], acc[nt][1], acc[nt][2], acc[nt][3],
                     al0, al1, al2, al3, bh0, bh1);
        }
    }
    __syncwarp();

    // scatter fragments into own x region (aliased epi buffer, stride 66)
    float* epiw = (float*)(s_x + w * NWREG);
#pragma unroll
    for (int nt = 0; nt < 8; ++nt) {
        const int c = nt * 8 + 2 * q;
        *(float2*)(epiw + g * 66 + c)       = make_float2(acc[nt][0], acc[nt][1]);
        *(float2*)(epiw + (g + 8) * 66 + c) = make_float2(acc[nt][2], acc[nt][3]);
    }
    __syncwarp();

    float* out = (which == 0) ? g_fni : (which == 1) ? g_fnj : g_hsrc;
    const float bb0 = sb[2 * lane];
    const float bb1 = sb[2 * lane + 1];
    const int rowbase = nbase + w * 16;
#pragma unroll 4
    for (int r = 0; r < 16; ++r) {
        if (rowbase + r >= N) break;
        float2 v = *(const float2*)(epiw + r * 66 + 2 * lane);
        *(float2*)(out + (size_t)(rowbase + r) * 64 + 2 * lane) =
            make_float2(v.x + bb0, v.y + bb1);
    }
}

// ---------------------------------------------------------------------------
// Kernel 2: edge pass 1 via tensor cores (bf16x3) — unchanged from R7.
// ---------------------------------------------------------------------------
__global__ __launch_bounds__(256, 4)
void edge_main(const float* __restrict__ efeats,
               const int*   __restrict__ src,
               const int*   __restrict__ dst,
               const float* __restrict__ attn,
               const float* __restrict__ bias_e,
               float* __restrict__ out_e,
               int E)
{
    extern __shared__ char dyns[];
    unsigned* s_wh = (unsigned*)dyns;                    // 64*WS u32
    unsigned* s_wl = s_wh + 64 * WS;
    unsigned* s_x  = s_wl + 64 * WS;                     // 8 * WREG u32
    float*    s_attn = (float*)(s_x + 8 * WREG);
    float*    s_bias = s_attn + 64;

    const int tid  = threadIdx.x;
    const int lane = tid & 31;
    const int w    = tid >> 5;

    for (int j = tid; j < 2048; j += 256) {
        int n = j >> 5, kp = j & 31;
        s_wh[n * WS + kp] = g_wth[j];
        s_wl[n * WS + kp] = g_wtl[j];
    }
    if (tid < 64) {
        s_attn[tid] = attn[tid];
        s_bias[tid] = bias_e[tid];
    }

    const long long eblk = (long long)blockIdx.x * 128;
    {
        const float4* ef4 = (const float4*)efeats;
#pragma unroll
        for (int i = 0; i < 8; ++i) {
            int idx = i * 256 + tid;
            int e  = idx >> 4;
            int ch = idx & 15;
            float4 v = make_float4(0.f, 0.f, 0.f, 0.f);
            if (eblk + e < E) v = ef4[(eblk + e) * 16 + ch];
            unsigned h0 = bf16pack(v.x, v.y);
            unsigned h1 = bf16pack(v.z, v.w);
            unsigned l0 = bf16pack(bf16residual(v.x), bf16residual(v.y));
            unsigned l1 = bf16pack(bf16residual(v.z), bf16residual(v.w));
            unsigned* base = s_x + (e >> 4) * WREG + (e & 15) * XS + ch * 2;
            *(uint2*)(base)            = make_uint2(h0, h1);
            *(uint2*)(base + 16 * XS)  = make_uint2(l0, l1);
        }
    }
    __syncthreads();

    const long long ewarp = eblk + w * 16;
    const int g = lane >> 2;
    const int q = lane & 3;

    int myS = 0, myD = 0;
    if (lane < 16 && ewarp + lane < E) {
        myS = src[ewarp + lane];
        myD = dst[ewarp + lane];
    }

    float acc[8][4];
#pragma unroll
    for (int nt = 0; nt < 8; ++nt)
#pragma unroll
        for (int i = 0; i < 4; ++i) acc[nt][i] = 0.0f;

    const unsigned* xh0 = s_x + w * WREG + g * XS;
    const unsigned* xh8 = xh0 + 8 * XS;
    const unsigned* xl0 = xh0 + 16 * XS;
    const unsigned* xl8 = xl0 + 8 * XS;

#pragma unroll
    for (int kt = 0; kt < 4; ++kt) {
        const int kp = kt * 8 + q;
        unsigned ah0 = xh0[kp],     ah1 = xh8[kp];
        unsigned ah2 = xh0[kp + 4], ah3 = xh8[kp + 4];
        unsigned al0 = xl0[kp],     al1 = xl8[kp];
        unsigned al2 = xl0[kp + 4], al3 = xl8[kp + 4];
#pragma unroll
        for (int nt = 0; nt < 8; ++nt) {
            const unsigned* wb  = s_wh + (nt * 8 + g) * WS + kp;
            const unsigned* wlb = s_wl + (nt * 8 + g) * WS + kp;
            unsigned bh0 = wb[0],  bh1 = wb[4];
            unsigned bl0 = wlb[0], bl1 = wlb[4];
            mma16816(acc[nt][0], acc[nt][1], acc[nt][2], acc[nt][3],
                     ah0, ah1, ah2, ah3, bh0, bh1);
            mma16816(acc[nt][0], acc[nt][1], acc[nt][2], acc[nt][3],
                     ah0, ah1, ah2, ah3, bl0, bl1);
            mma16816(acc[nt][0], acc[nt][1], acc[nt][2], acc[nt][3],
                     al0, al1, al2, al3, bh0, bh1);
        }
    }
    __syncwarp();

    float* epiw = (float*)(s_x + w * WREG);
#pragma unroll
    for (int nt = 0; nt < 8; ++nt) {
        const int c = nt * 8 + 2 * q;
        *(float2*)(epiw + g * 66 + c)       = make_float2(acc[nt][0], acc[nt][1]);
        *(float2*)(epiw + (g + 8) * 66 + c) = make_float2(acc[nt][2], acc[nt][3]);
    }
    __syncwarp();

    const float b0 = s_bias[2 * lane];
    const float b1 = s_bias[2 * lane + 1];
    const float a0 = s_attn[2 * lane];
    const float a1 = s_attn[2 * lane + 1];

    for (int r = 0; r < 16; ++r) {
        long long e_r = ewarp + r;
        if (e_r >= E) break;
        const int s_r = __shfl_sync(0xffffffffu, myS, r);
        const int d_r = __shfl_sync(0xffffffffu, myD, r);

        float2 fa = *(const float2*)(g_fni + (size_t)s_r * 64 + 2 * lane);
        float2 fb = *(const float2*)(g_fnj + (size_t)d_r * 64 + 2 * lane);
        float2 ac = *(const float2*)(epiw + r * 66 + 2 * lane);

        float y0 = ac.x + fa.x + fb.x + b0;
        float y1 = ac.y + fa.y + fb.y + b1;
        y0 = (y0 > 0.0f) ? y0 : 0.01f * y0;
        y1 = (y1 > 0.0f) ? y1 : 0.01f * y1;

        float lp = y0 * a0 + y1 * a1;
        lp += __shfl_xor_sync(0xffffffffu, lp, 4);
        lp += __shfl_xor_sync(0xffffffffu, lp, 2);
        lp += __shfl_xor_sync(0xffffffffu, lp, 1);

        y0 += __shfl_xor_sync(0xffffffffu, y0, 8);
        y0 += __shfl_xor_sync(0xffffffffu, y0, 16);
        y1 += __shfl_xor_sync(0xffffffffu, y1, 8);
        y1 += __shfl_xor_sync(0xffffffffu, y1, 16);

        float l1v = __shfl_sync(0xffffffffu, lp, 8);
        float l2v = __shfl_sync(0xffffffffu, lp, 16);
        float l3v = __shfl_sync(0xffffffffu, lp, 24);

        if (lane < 8)
            *(float2*)(out_e + (size_t)e_r * 16 + 2 * lane) =
                make_float2(0.25f * y0, 0.25f * y1);

        if (lane == 0) {
            float e0 = expf(lp),  e1 = expf(l1v);
            float e2 = expf(l2v), e3 = expf(l3v);
            *(float4*)(g_ex + (size_t)e_r * 4) = make_float4(e0, e1, e2, e3);
            red_add_v4(&g_z[(size_t)d_r * 4], e0, e1, e2, e3);
        }
    }
}

// ---------------------------------------------------------------------------
// Kernel 3: invert z once per (node, head)
// ---------------------------------------------------------------------------
__global__ void inv_z(int N) {
    int i = blockIdx.x * 256 + threadIdx.x;
    if (i < N * 4) g_z[i] = __frcp_rn(g_z[i]);
}

// ---------------------------------------------------------------------------
// Kernel 4: edge pass 2.  4 lanes/edge; lane t owns dims 4t..4t+3; v4 RED.
// ---------------------------------------------------------------------------
__global__ __launch_bounds__(256)
void edge_aggr(const int* __restrict__ src,
               const int* __restrict__ dst,
               float* __restrict__ out_n,
               int E)
{
    const int tid  = threadIdx.x;
    const int lane = tid & 31;
    const int t    = lane & 3;
    const int le   = (tid >> 5) * 8 + (lane >> 2);
    const long long e = (long long)blockIdx.x * 64 + le;
    if (e >= E) return;

    const int s = src[e];
    const int d = dst[e];

    float4 ex4 = *(const float4*)(g_ex + (size_t)e * 4);
    float4 zi4 = *(const float4*)(g_z  + (size_t)d * 4);
    const float a0 = 0.25f * ex4.x * zi4.x;
    const float a1 = 0.25f * ex4.y * zi4.y;
    const float a2 = 0.25f * ex4.z * zi4.z;
    const float a3 = 0.25f * ex4.w * zi4.w;

    const float* hr = g_hsrc + (size_t)s * 64 + 4 * t;
    float4 v0 = *(const float4*)(hr);
    float4 v1 = *(const float4*)(hr + 16);
    float4 v2 = *(const float4*)(hr + 32);
    float4 v3 = *(const float4*)(hr + 48);

    float m0 = a0 * v0.x + a1 * v1.x + a2 * v2.x + a3 * v3.x;
    float m1 = a0 * v0.y + a1 * v1.y + a2 * v2.y + a3 * v3.y;
    float m2 = a0 * v0.z + a1 * v1.z + a2 * v2.z + a3 * v3.z;
    float m3 = a0 * v0.w + a1 * v1.w + a2 * v2.w + a3 * v3.w;

    red_add_v4(out_n + (size_t)d * 16 + 4 * t, m0, m1, m2, m3);
}

// ---------------------------------------------------------------------------
extern "C" void kernel_launch(void* const* d_in, const int* in_sizes, int n_in,
                              void* d_out, int out_size)
{
    const float* nfeats = (const float*)d_in[0];
    const float* efeats = (const float*)d_in[1];
    const int*   src    = (const int*)  d_in[2];
    const int*   dst    = (const int*)  d_in[3];
    const float* Wni    = (const float*)d_in[4];
    const float* Wnj    = (const float*)d_in[5];
    const float* Wfij   = (const float*)d_in[6];
    const float* Wsrc   = (const float*)d_in[7];
    const float* bsrc   = (const float*)d_in[8];
    const float* attn   = (const float*)d_in[9];
    const float* biase  = (const float*)d_in[10];

    const int N = in_sizes[0] / 128;
    const int E = in_sizes[2];

    float* out_n = (float*)d_out;
    float* out_e = out_n + (size_t)N * 16;

    static int smem_set = 0;
    const int EM_SMEM = (64 * WS * 2 + 8 * WREG + 128) * 4;        // 55808 B
    const int NM_SMEM = (64 * NXS * 2 + 8 * NWREG + 64) * 4;       // 104704 B
    if (!smem_set) {
        cudaFuncSetAttribute(edge_main,
                             cudaFuncAttributeMaxDynamicSharedMemorySize,
                             EM_SMEM);
        cudaFuncSetAttribute(node_mma,
                             cudaFuncAttributeMaxDynamicSharedMemorySize,
                             NM_SMEM);
        smem_set = 1;
    }

    // launch order: idx 3 (ncu's pick) = node_mma this round
    zero_n<<<(N * 16 + 255) / 256, 256>>>(out_n, N);

    zero_z<<<(N * 4 + 255) / 256, 256>>>(N);

    wsplit_all<<<56, 256>>>(Wfij, Wni, Wnj, Wsrc);

    dim3 gn((N + 127) / 128, 3);
    node_mma<<<gn, 256, NM_SMEM>>>(nfeats, bsrc, N);

    edge_main<<<(E + 127) / 128, 256, EM_SMEM>>>(efeats, src, dst,
                                                 attn, biase, out_e, E);

    inv_z<<<(N * 4 + 255) / 256, 256>>>(N);

    edge_aggr<<<(E + 63) / 64, 256>>>(src, dst, out_n, E);
}